// round 4
// baseline (speedup 1.0000x reference)
#include <cuda_runtime.h>
#include <cstdint>

#define B_   4
#define H_   8
#define LQ   1024
#define DH   64
#define KL   1024
#define NJ   33      // 2*MAX_REL_POS + 1
#define NJP  36      // padded stride for S
#define MAXREL 16

// Scratch: S[b][h][q][j] with j-stride NJP. 4*8*1024*36 floats = 4.7MB.
__device__ float g_S[B_ * H_ * LQ * NJP];

// ---------------------------------------------------------------------------
// Kernel 1: S[b,h,q,j] = dot(query[b,h,q,:], rel_table[j,:])
// grid (LQ/128, H, B), block (9,32)=288. 4q x 4j register tile per thread.
// ---------------------------------------------------------------------------
__global__ void __launch_bounds__(288) compute_s_kernel(
    const float* __restrict__ query,
    const float* __restrict__ table)
{
    __shared__ float qS[128][DH + 1];
    __shared__ float tT[DH][NJP];

    const int tid   = threadIdx.y * 9 + threadIdx.x;
    const int qBase = blockIdx.x * 128;
    const int h     = blockIdx.y;
    const int b     = blockIdx.z;

    const float* qptr = query + (size_t)(((b * H_ + h) * LQ) + qBase) * DH;

    for (int i = tid; i < 128 * DH / 4; i += 288) {
        float4 v = ((const float4*)qptr)[i];
        int qr = i >> 4;
        int d0 = (i & 15) << 2;
        qS[qr][d0 + 0] = v.x; qS[qr][d0 + 1] = v.y;
        qS[qr][d0 + 2] = v.z; qS[qr][d0 + 3] = v.w;
    }
    for (int i = tid; i < NJ * DH / 4; i += 288) {
        float4 v = ((const float4*)table)[i];
        int j  = i >> 4;
        int d0 = (i & 15) << 2;
        tT[d0 + 0][j] = v.x; tT[d0 + 1][j] = v.y;
        tT[d0 + 2][j] = v.z; tT[d0 + 3][j] = v.w;
    }
    for (int i = tid; i < DH * 3; i += 288) tT[i / 3][NJ + (i % 3)] = 0.f;
    __syncthreads();

    const int q0 = threadIdx.y * 4;
    const int j0 = threadIdx.x * 4;

    float acc[4][4] = {};
    #pragma unroll 8
    for (int d = 0; d < DH; d++) {
        float4 tv = *(const float4*)(&tT[d][j0]);
        #pragma unroll
        for (int i = 0; i < 4; i++) {
            float qv = qS[q0 + i][d];
            acc[i][0] += qv * tv.x;
            acc[i][1] += qv * tv.y;
            acc[i][2] += qv * tv.z;
            acc[i][3] += qv * tv.w;
        }
    }

    float* sp = g_S + (size_t)(((b * H_ + h) << 10) + qBase + q0) * NJP + j0;
    #pragma unroll
    for (int i = 0; i < 4; i++) {
        float4 o = make_float4(acc[i][0], acc[i][1], acc[i][2], acc[i][3]);
        *(float4*)(sp + i * NJP) = o;
    }
}

// ---------------------------------------------------------------------------
// Kernel 2: out[b,h,q,k] = S[b,h,q, clip(ts[b,k]-ts[b,q])+16]
// grid (LQ/4, B), block 256. 4 q-rows per block; each thread owns 4 k's.
// s2 transposed [q][j][h]: one LDS.128 fetches 4 heads at once.
// Fast path: sorted ts => if i0==i3 all four indices equal (2 LDS.128 total).
// ---------------------------------------------------------------------------
__global__ void __launch_bounds__(256) gather_kernel(
    const int* __restrict__ time_ids,
    float* __restrict__ out)
{
    __shared__ float s2[4][NJ][H_];   // [q_local][j][h]
    __shared__ int   s_tq[4];

    const int qBase = blockIdx.x * 4;
    const int b     = blockIdx.y;
    const int tid   = threadIdx.x;

    for (int i = tid; i < 4 * H_ * NJ; i += 256) {
        int ql = i / (H_ * NJ);
        int r  = i - ql * (H_ * NJ);
        int h  = r / NJ;
        int j  = r - h * NJ;
        s2[ql][j][h] = g_S[(size_t)(((b * H_ + h) << 10) + qBase + ql) * NJP + j];
    }
    const int* tsb = time_ids + b * KL;
    if (tid < 4) s_tq[tid] = tsb[qBase + tid];
    __syncthreads();

    const int k0 = tid * 4;
    const int4 tk = *(const int4*)(tsb + k0);

    #pragma unroll
    for (int ql = 0; ql < 4; ql++) {
        const int tq = s_tq[ql];
        const int i0 = min(max(tk.x - tq, -MAXREL), MAXREL) + MAXREL;
        const int i3 = min(max(tk.w - tq, -MAXREL), MAXREL) + MAXREL;

        float* op = out + ((((size_t)(b * H_) << 10) + (qBase + ql)) << 10) + k0;

        if (i0 == i3) {
            // All four k's share one index: broadcast fill.
            float4 A = *(const float4*)&s2[ql][i0][0];   // h0..h3
            float4 Bv = *(const float4*)&s2[ql][i0][4];  // h4..h7
            *(float4*)(op + ((size_t)0 << 20)) = make_float4(A.x, A.x, A.x, A.x);
            *(float4*)(op + ((size_t)1 << 20)) = make_float4(A.y, A.y, A.y, A.y);
            *(float4*)(op + ((size_t)2 << 20)) = make_float4(A.z, A.z, A.z, A.z);
            *(float4*)(op + ((size_t)3 << 20)) = make_float4(A.w, A.w, A.w, A.w);
            *(float4*)(op + ((size_t)4 << 20)) = make_float4(Bv.x, Bv.x, Bv.x, Bv.x);
            *(float4*)(op + ((size_t)5 << 20)) = make_float4(Bv.y, Bv.y, Bv.y, Bv.y);
            *(float4*)(op + ((size_t)6 << 20)) = make_float4(Bv.z, Bv.z, Bv.z, Bv.z);
            *(float4*)(op + ((size_t)7 << 20)) = make_float4(Bv.w, Bv.w, Bv.w, Bv.w);
        } else {
            const int i1 = min(max(tk.y - tq, -MAXREL), MAXREL) + MAXREL;
            const int i2 = min(max(tk.z - tq, -MAXREL), MAXREL) + MAXREL;
            float4 A0 = *(const float4*)&s2[ql][i0][0];
            float4 A1 = *(const float4*)&s2[ql][i1][0];
            float4 A2 = *(const float4*)&s2[ql][i2][0];
            float4 A3 = *(const float4*)&s2[ql][i3][0];
            float4 B0 = *(const float4*)&s2[ql][i0][4];
            float4 B1 = *(const float4*)&s2[ql][i1][4];
            float4 B2 = *(const float4*)&s2[ql][i2][4];
            float4 B3 = *(const float4*)&s2[ql][i3][4];
            *(float4*)(op + ((size_t)0 << 20)) = make_float4(A0.x, A1.x, A2.x, A3.x);
            *(float4*)(op + ((size_t)1 << 20)) = make_float4(A0.y, A1.y, A2.y, A3.y);
            *(float4*)(op + ((size_t)2 << 20)) = make_float4(A0.z, A1.z, A2.z, A3.z);
            *(float4*)(op + ((size_t)3 << 20)) = make_float4(A0.w, A1.w, A2.w, A3.w);
            *(float4*)(op + ((size_t)4 << 20)) = make_float4(B0.x, B1.x, B2.x, B3.x);
            *(float4*)(op + ((size_t)5 << 20)) = make_float4(B0.y, B1.y, B2.y, B3.y);
            *(float4*)(op + ((size_t)6 << 20)) = make_float4(B0.z, B1.z, B2.z, B3.z);
            *(float4*)(op + ((size_t)7 << 20)) = make_float4(B0.w, B1.w, B2.w, B3.w);
        }
    }
}

// ---------------------------------------------------------------------------
extern "C" void kernel_launch(void* const* d_in, const int* in_sizes, int n_in,
                              void* d_out, int out_size)
{
    const float* query    = (const float*)d_in[0];   // [4,8,1024,64]
    const float* table    = (const float*)d_in[1];   // [33,64]
    const int*   time_ids = (const int*)d_in[2];     // [4,1024] int32
    float*       out      = (float*)d_out;           // [4,8,1024,1024]

    dim3 g1(LQ / 128, H_, B_);
    dim3 b1(9, 32, 1);
    compute_s_kernel<<<g1, b1>>>(query, table);

    dim3 g2(LQ / 4, B_);
    gather_kernel<<<g2, 256>>>(time_ids, out);
}

// round 6
// speedup vs baseline: 1.1052x; 1.1052x over previous
#include <cuda_runtime.h>
#include <cstdint>

#define B_   4
#define H_   8
#define LQ   1024
#define DH   64
#define KL   1024
#define NJ   33      // 2*MAX_REL_POS + 1
#define NJP  36      // padded stride for S (and j-tile coverage: 9 groups * 4)
#define MAXREL 16
#define QPAD 132     // qT row stride (128 + 4)

// Scratch: S[b][h][q][j] with j-stride NJP. 4*8*1024*36 floats = 4.7MB.
__device__ float g_S[B_ * H_ * LQ * NJP];

__device__ __forceinline__ unsigned long long pack_dup(float v) {
    unsigned long long r;
    unsigned int b = __float_as_uint(v);
    asm("mov.b64 %0, {%1, %1};" : "=l"(r) : "r"(b));
    return r;
}
__device__ __forceinline__ unsigned long long fma2(unsigned long long a,
                                                   unsigned long long b,
                                                   unsigned long long c) {
    unsigned long long d;
    asm("fma.rn.f32x2 %0, %1, %2, %3;" : "=l"(d) : "l"(a), "l"(b), "l"(c));
    return d;
}
__device__ __forceinline__ float2 unpack2(unsigned long long p) {
    unsigned int lo, hi;
    asm("mov.b64 {%0, %1}, %2;" : "=r"(lo), "=r"(hi) : "l"(p));
    return make_float2(__uint_as_float(lo), __uint_as_float(hi));
}

// ---------------------------------------------------------------------------
// Kernel 1: S[b,h,q,j] = dot(query[b,h,q,:], rel_table[j,:])
// grid (LQ/128, H, B), block (9,32)=288. Thread tile: 4q x 4j.
// j-axis packed into f32x2 pairs; q read via transposed qT (LDS.128, warp-
// broadcast across the 9 j-groups). Inner loop: 2 LDS.128 + 4 mov + 8 FFMA2.
// ---------------------------------------------------------------------------
__global__ void __launch_bounds__(288) compute_s_kernel(
    const float* __restrict__ query,
    const float* __restrict__ table)
{
    __shared__ float qT[DH][QPAD];   // transposed query tile [d][q]
    __shared__ float tT[DH][NJP];    // transposed table [d][j]

    const int tid   = threadIdx.y * 9 + threadIdx.x;
    const int qBase = blockIdx.x * 128;
    const int h     = blockIdx.y;
    const int b     = blockIdx.z;

    const float* qptr = query + (size_t)(((b * H_ + h) * LQ) + qBase) * DH;

    // Load 128x64 query tile, transposed into qT[d][q]
    for (int i = tid; i < 128 * DH / 4; i += 288) {
        float4 v = ((const float4*)qptr)[i];
        int qr = i >> 4;
        int d0 = (i & 15) << 2;
        qT[d0 + 0][qr] = v.x; qT[d0 + 1][qr] = v.y;
        qT[d0 + 2][qr] = v.z; qT[d0 + 3][qr] = v.w;
    }
    // Load 33x64 table, transposed into tT[d][j]
    for (int i = tid; i < NJ * DH / 4; i += 288) {
        float4 v = ((const float4*)table)[i];
        int j  = i >> 4;
        int d0 = (i & 15) << 2;
        tT[d0 + 0][j] = v.x; tT[d0 + 1][j] = v.y;
        tT[d0 + 2][j] = v.z; tT[d0 + 3][j] = v.w;
    }
    // Zero pad columns j = 33..35
    for (int i = tid; i < DH * 3; i += 288) tT[i / 3][NJ + (i % 3)] = 0.f;
    __syncthreads();

    const int j0 = threadIdx.x * 4;   // 0..32
    const int q0 = threadIdx.y * 4;   // 0..124

    unsigned long long acc[4][2];
    #pragma unroll
    for (int i = 0; i < 4; i++) { acc[i][0] = 0ull; acc[i][1] = 0ull; }

    #pragma unroll 8
    for (int d = 0; d < DH; d++) {
        // two j-pairs (j0..j0+3) in one 16B LDS
        ulonglong2 tp = *(const ulonglong2*)(&tT[d][j0]);
        // four q values in one 16B LDS (broadcast across x within warp)
        float4 qv = *(const float4*)(&qT[d][q0]);
        unsigned long long qq0 = pack_dup(qv.x);
        unsigned long long qq1 = pack_dup(qv.y);
        unsigned long long qq2 = pack_dup(qv.z);
        unsigned long long qq3 = pack_dup(qv.w);
        acc[0][0] = fma2(qq0, tp.x, acc[0][0]);
        acc[0][1] = fma2(qq0, tp.y, acc[0][1]);
        acc[1][0] = fma2(qq1, tp.x, acc[1][0]);
        acc[1][1] = fma2(qq1, tp.y, acc[1][1]);
        acc[2][0] = fma2(qq2, tp.x, acc[2][0]);
        acc[2][1] = fma2(qq2, tp.y, acc[2][1]);
        acc[3][0] = fma2(qq3, tp.x, acc[3][0]);
        acc[3][1] = fma2(qq3, tp.y, acc[3][1]);
    }

    float* sp = g_S + (size_t)(((b * H_ + h) << 10) + qBase + q0) * NJP + j0;
    #pragma unroll
    for (int i = 0; i < 4; i++) {
        float2 a = unpack2(acc[i][0]);
        float2 c = unpack2(acc[i][1]);
        *(float4*)(sp + i * NJP) = make_float4(a.x, a.y, c.x, c.y);
    }
}

// ---------------------------------------------------------------------------
// Kernel 2 (EXACT round-3 version, 24.1us known-good):
// out[b,h,q,k] = S[b,h,q, clip(ts[b,k]-ts[b,q],-16,16)+16]
// grid (LQ, B), block 256. Each thread handles 4 consecutive k for all 8 h.
// ---------------------------------------------------------------------------
__global__ void __launch_bounds__(256) gather_kernel(
    const int* __restrict__ time_ids,
    float* __restrict__ out)
{
    __shared__ float s_sm[H_][NJ];

    const int q   = blockIdx.x;
    const int b   = blockIdx.y;
    const int tid = threadIdx.x;

    // H_*NJ = 264 > 256 threads: stride this loop.
    for (int i = tid; i < H_ * NJ; i += 256) {
        int h = i / NJ;
        int j = i - h * NJ;
        s_sm[h][j] = g_S[(size_t)(((b * H_ + h) << 10) + q) * NJP + j];
    }

    const int* tsb = time_ids + b * KL;
    const int  tq  = tsb[q];
    __syncthreads();

    const int k0 = tid * 4;
    int4 tk = *(const int4*)(tsb + k0);

    int i0 = min(max(tk.x - tq, -MAXREL), MAXREL) + MAXREL;
    int i1 = min(max(tk.y - tq, -MAXREL), MAXREL) + MAXREL;
    int i2 = min(max(tk.z - tq, -MAXREL), MAXREL) + MAXREL;
    int i3 = min(max(tk.w - tq, -MAXREL), MAXREL) + MAXREL;

    float* op = out + ((size_t)(b * H_ * LQ + q) << 10) + k0;
    #pragma unroll
    for (int h = 0; h < H_; h++) {
        float4 o = make_float4(s_sm[h][i0], s_sm[h][i1], s_sm[h][i2], s_sm[h][i3]);
        *(float4*)(op + ((size_t)h << 20)) = o;
    }
}

// ---------------------------------------------------------------------------
extern "C" void kernel_launch(void* const* d_in, const int* in_sizes, int n_in,
                              void* d_out, int out_size)
{
    const float* query    = (const float*)d_in[0];   // [4,8,1024,64]
    const float* table    = (const float*)d_in[1];   // [33,64]
    const int*   time_ids = (const int*)d_in[2];     // [4,1024] int32
    float*       out      = (float*)d_out;           // [4,8,1024,1024]

    dim3 g1(LQ / 128, H_, B_);
    dim3 b1(9, 32, 1);
    compute_s_kernel<<<g1, b1>>>(query, table);

    dim3 g2(LQ, B_);
    gather_kernel<<<g2, 256>>>(time_ids, out);
}